// round 1
// baseline (speedup 1.0000x reference)
#include <cuda_runtime.h>
#include <math.h>
#include <stdint.h>

// Problem constants
#define BB 2
#define SS 2048
#define HH 1024
#define FF 2816
#define EE 8
#define KK 2
#define TT (BB*SS)          // 4096 tokens
#define SLOTS (TT*KK)       // 8192 token-slots
#define BM 64               // row tile (slots)
#define PADMAX (SLOTS + EE*BM)   // 8704 worst-case padded rows
#define ROW_TILES_MAX (PADMAX/BM) // 136

// ---------------- device scratch (static, allowed) ----------------
__device__ float g_h1[(size_t)PADMAX * FF];   // hidden after silu(gate)*up  (~98MB)
__device__ float g_y [(size_t)PADMAX * HH];   // expert outputs per slot-row (~36MB)
__device__ int   g_count[EE];
__device__ int   g_fill[EE];
__device__ float g_psum[EE];
__device__ int   g_base[EE+1];                // padded bases, g_base[EE] = total padded rows
__device__ int   g_sorted_token[PADMAX];      // token id per sorted row (0 for pad rows)
__device__ int   g_slot_row[SLOTS];           // (t,k) -> sorted row
__device__ int   g_tok_e[SLOTS];
__device__ float g_tok_w[SLOTS];

// ---------------- init: reset counters each launch ----------------
__global__ void init_kernel() {
    int i = blockIdx.x * blockDim.x + threadIdx.x;
    if (i < PADMAX) g_sorted_token[i] = 0;
    if (i < EE) { g_count[i] = 0; g_fill[i] = 0; g_psum[i] = 0.f; }
}

// ---------------- router: logits, top-2, softmax weights, aux stats ----------------
__global__ void router_kernel(const float* __restrict__ x, const float* __restrict__ rw) {
    int t = blockIdx.x;
    __shared__ float sp[128][EE];
    float acc[EE];
#pragma unroll
    for (int e = 0; e < EE; e++) acc[e] = 0.f;
    const float* xt = x + (size_t)t * HH;
    for (int h = threadIdx.x; h < HH; h += 128) {
        float xv = xt[h];
#pragma unroll
        for (int e = 0; e < EE; e++) acc[e] += xv * rw[e*HH + h];
    }
#pragma unroll
    for (int e = 0; e < EE; e++) sp[threadIdx.x][e] = acc[e];
    __syncthreads();
    for (int s = 64; s > 0; s >>= 1) {
        if (threadIdx.x < s) {
#pragma unroll
            for (int e = 0; e < EE; e++) sp[threadIdx.x][e] += sp[threadIdx.x + s][e];
        }
        __syncthreads();
    }
    if (threadIdx.x == 0) {
        float lg[EE];
#pragma unroll
        for (int e = 0; e < EE; e++) lg[e] = sp[0][e];
        // top-2, first occurrence wins ties (matches lax.top_k)
        int i0 = 0;
#pragma unroll
        for (int e = 1; e < EE; e++) if (lg[e] > lg[i0]) i0 = e;
        int i1 = -1;
#pragma unroll
        for (int e = 0; e < EE; e++) {
            if (e == i0) continue;
            if (i1 < 0 || lg[e] > lg[i1]) i1 = e;
        }
        float ex = expf(lg[i1] - lg[i0]);
        float w0 = 1.f / (1.f + ex);
        float w1 = ex / (1.f + ex);
        g_tok_e[2*t]   = i0;  g_tok_e[2*t+1] = i1;
        g_tok_w[2*t]   = w0;  g_tok_w[2*t+1] = w1;
        atomicAdd(&g_count[i0], 1);
        atomicAdd(&g_count[i1], 1);
        // full softmax for aux loss
        float m = lg[0];
#pragma unroll
        for (int e = 1; e < EE; e++) m = fmaxf(m, lg[e]);
        float s = 0.f;
        float pe[EE];
#pragma unroll
        for (int e = 0; e < EE; e++) { pe[e] = expf(lg[e] - m); s += pe[e]; }
        float inv = 1.f / s;
#pragma unroll
        for (int e = 0; e < EE; e++) atomicAdd(&g_psum[e], pe[e] * inv);
    }
}

// ---------------- setup: padded prefix bases + aux loss ----------------
__global__ void setup_kernel(float* __restrict__ out_aux) {
    if (threadIdx.x == 0) {
        int base = 0;
        for (int e = 0; e < EE; e++) {
            g_base[e] = base;
            int pc = (g_count[e] + BM - 1) & ~(BM - 1);
            base += pc;
        }
        g_base[EE] = base;
        float aux = 0.f;
        for (int e = 0; e < EE; e++) {
            float f = (float)g_count[e] / (float)SLOTS;
            float P = g_psum[e] / (float)TT;
            aux += f * P;
        }
        out_aux[0] = aux * (float)EE;
    }
}

// ---------------- scatter slots into expert-sorted rows ----------------
__global__ void scatter_kernel() {
    int s = blockIdx.x * blockDim.x + threadIdx.x;
    if (s >= SLOTS) return;
    int e = g_tok_e[s];
    int pos = atomicAdd(&g_fill[e], 1);
    int row = g_base[e] + pos;
    g_sorted_token[row] = s >> 1;
    g_slot_row[s] = row;
}

// ---------------- GEMM1: h1 = silu(x@Wg) * (x@Wu), grouped by expert ----------------
__global__ __launch_bounds__(256) void gemm1_kernel(
    const float* __restrict__ x,
    const float* __restrict__ wg,
    const float* __restrict__ wu)
{
    int rt = blockIdx.x;           // row tile (fastest -> L2 reuse of B tiles)
    int nt = blockIdx.y;           // F tile
    int total = g_base[EE];
    int r0 = rt * BM;
    if (r0 >= total) return;
    int e = 0;
    while (g_base[e+1] <= r0) e++;
    const float* Wg = wg + (size_t)e * HH * FF;
    const float* Wu = wu + (size_t)e * HH * FF;
    int n0 = nt * 64;

    __shared__ float As[16][64];
    __shared__ float Bg[16][64];
    __shared__ float Bu[16][64];
    __shared__ int   s_tok[64];

    int tid = threadIdx.x;
    if (tid < 64) s_tok[tid] = g_sorted_token[r0 + tid];
    __syncthreads();

    int tx = tid & 15, ty = tid >> 4;
    int arow = tid >> 2, akq = tid & 3;      // A loader: row 0..63, quad 0..3
    int brow = tid >> 4, bcol = (tid & 15) * 4; // B loader: row 0..15, col quad

    float accg[4][4], accu[4][4];
#pragma unroll
    for (int i = 0; i < 4; i++)
#pragma unroll
        for (int j = 0; j < 4; j++) { accg[i][j] = 0.f; accu[i][j] = 0.f; }

    const float* xrow = x + (size_t)s_tok[arow] * HH;

    for (int kk = 0; kk < HH; kk += 16) {
        float4 av = *(const float4*)(xrow + kk + akq * 4);
        As[akq*4+0][arow] = av.x;
        As[akq*4+1][arow] = av.y;
        As[akq*4+2][arow] = av.z;
        As[akq*4+3][arow] = av.w;
        *(float4*)&Bg[brow][bcol] = *(const float4*)(Wg + (size_t)(kk + brow) * FF + n0 + bcol);
        *(float4*)&Bu[brow][bcol] = *(const float4*)(Wu + (size_t)(kk + brow) * FF + n0 + bcol);
        __syncthreads();
#pragma unroll
        for (int k = 0; k < 16; k++) {
            float4 a  = *(float4*)&As[k][ty*4];
            float4 bg = *(float4*)&Bg[k][tx*4];
            float4 bu = *(float4*)&Bu[k][tx*4];
            float ar[4] = {a.x, a.y, a.z, a.w};
            float bgr[4] = {bg.x, bg.y, bg.z, bg.w};
            float bur[4] = {bu.x, bu.y, bu.z, bu.w};
#pragma unroll
            for (int i = 0; i < 4; i++)
#pragma unroll
                for (int j = 0; j < 4; j++) {
                    accg[i][j] += ar[i] * bgr[j];
                    accu[i][j] += ar[i] * bur[j];
                }
        }
        __syncthreads();
    }
#pragma unroll
    for (int i = 0; i < 4; i++) {
        size_t rowoff = (size_t)(r0 + ty*4 + i) * FF + n0;
#pragma unroll
        for (int j = 0; j < 4; j++) {
            float g = accg[i][j];
            float u = accu[i][j];
            float h = (g / (1.f + expf(-g))) * u;
            g_h1[rowoff + tx*4 + j] = h;
        }
    }
}

// ---------------- GEMM2: y = h1 @ Wd, grouped by expert ----------------
__global__ __launch_bounds__(256) void gemm2_kernel(const float* __restrict__ wd)
{
    int rt = blockIdx.x;
    int nt = blockIdx.y;
    int total = g_base[EE];
    int r0 = rt * BM;
    if (r0 >= total) return;
    int e = 0;
    while (g_base[e+1] <= r0) e++;
    const float* Wd = wd + (size_t)e * FF * HH;
    int n0 = nt * 64;

    __shared__ float As[16][64];
    __shared__ float Bs[16][64];

    int tid = threadIdx.x;
    int tx = tid & 15, ty = tid >> 4;
    int arow = tid >> 2, akq = tid & 3;
    int brow = tid >> 4, bcol = (tid & 15) * 4;

    float acc[4][4];
#pragma unroll
    for (int i = 0; i < 4; i++)
#pragma unroll
        for (int j = 0; j < 4; j++) acc[i][j] = 0.f;

    const float* arowp = g_h1 + (size_t)(r0 + arow) * FF;

    for (int kk = 0; kk < FF; kk += 16) {
        float4 av = *(const float4*)(arowp + kk + akq * 4);
        As[akq*4+0][arow] = av.x;
        As[akq*4+1][arow] = av.y;
        As[akq*4+2][arow] = av.z;
        As[akq*4+3][arow] = av.w;
        *(float4*)&Bs[brow][bcol] = *(const float4*)(Wd + (size_t)(kk + brow) * HH + n0 + bcol);
        __syncthreads();
#pragma unroll
        for (int k = 0; k < 16; k++) {
            float4 a = *(float4*)&As[k][ty*4];
            float4 b = *(float4*)&Bs[k][tx*4];
            float ar[4] = {a.x, a.y, a.z, a.w};
            float br[4] = {b.x, b.y, b.z, b.w};
#pragma unroll
            for (int i = 0; i < 4; i++)
#pragma unroll
                for (int j = 0; j < 4; j++)
                    acc[i][j] += ar[i] * br[j];
        }
        __syncthreads();
    }
#pragma unroll
    for (int i = 0; i < 4; i++) {
        size_t rowoff = (size_t)(r0 + ty*4 + i) * HH + n0;
#pragma unroll
        for (int j = 0; j < 4; j++)
            g_y[rowoff + tx*4 + j] = acc[i][j];
    }
}

// ---------------- combine: out[t] = w0*y[slot0] + w1*y[slot1] ----------------
__global__ void combine_kernel(float* __restrict__ out) {
    int i = blockIdx.x * blockDim.x + threadIdx.x;   // over T * H/4
    if (i >= TT * (HH/4)) return;
    int t = i / (HH/4);
    int c = (i - t * (HH/4)) * 4;
    int r0 = g_slot_row[2*t], r1 = g_slot_row[2*t+1];
    float w0 = g_tok_w[2*t], w1 = g_tok_w[2*t+1];
    float4 y0 = *(const float4*)(g_y + (size_t)r0 * HH + c);
    float4 y1 = *(const float4*)(g_y + (size_t)r1 * HH + c);
    float4 o;
    o.x = w0*y0.x + w1*y1.x;
    o.y = w0*y0.y + w1*y1.y;
    o.z = w0*y0.z + w1*y1.z;
    o.w = w0*y0.w + w1*y1.w;
    *(float4*)(out + (size_t)t * HH + c) = o;
}

// ---------------- launch ----------------
extern "C" void kernel_launch(void* const* d_in, const int* in_sizes, int n_in,
                              void* d_out, int out_size) {
    const float* x  = (const float*)d_in[0];
    const float* rw = (const float*)d_in[1];
    const float* wg = (const float*)d_in[2];
    const float* wu = (const float*)d_in[3];
    const float* wd = (const float*)d_in[4];
    float* out = (float*)d_out;

    init_kernel<<<(PADMAX + 255) / 256, 256>>>();
    router_kernel<<<TT, 128>>>(x, rw);
    setup_kernel<<<1, 32>>>(out + (size_t)TT * HH);
    scatter_kernel<<<(SLOTS + 255) / 256, 256>>>();
    gemm1_kernel<<<dim3(ROW_TILES_MAX, FF/64), 256>>>(x, wg, wu);
    gemm2_kernel<<<dim3(ROW_TILES_MAX, HH/64), 256>>>(wd);
    combine_kernel<<<(TT * (HH/4) + 255) / 256, 256>>>(out);
}